// round 11
// baseline (speedup 1.0000x reference)
#include <cuda_runtime.h>
#include <cuda_bf16.h>
#include <cstdint>

#define N_NODES 50000
#define N_EDGES 800000
#define DIM 128
#define SCAN_BLK 512
#define NB ((N_NODES + SCAN_BLK - 1) / SCAN_BLK)   // 98

// ---------------- device scratch (static, allocation-free, zero-initialized) ----
__device__ float g_hs[(size_t)N_NODES * DIM];     // feature ping buffer
__device__ float g_hs2[(size_t)N_NODES * DIM];    // feature pong buffer
__device__ float g_norm_src[N_NODES];
__device__ float g_norm_dst[N_NODES];
__device__ int   g_deg[2 * N_NODES];              // [0,N) out-deg, [N,2N) in-deg
__device__ int   g_row_ptr[N_NODES + 1];          // CSR by dst
__device__ int   g_cursor[N_NODES];
__device__ int   g_blocksum[NB];
__device__ int   g_csr_src[N_EDGES];
// W fragment images: [layer][kstep(8)][ntile(16)][img(2)][lane(32)] of uint2
__device__ uint2 g_Bfrag[3 * 8 * 16 * 2 * 32];

// ---------------- prep kernels ----------------
__global__ void zero_deg_kernel() {
    int i = blockIdx.x * blockDim.x + threadIdx.x;
    if (i < 2 * N_NODES) g_deg[i] = 0;
}
__global__ void count_deg_kernel(const int* __restrict__ src, const int* __restrict__ dst) {
    int e = blockIdx.x * blockDim.x + threadIdx.x;
    if (e < N_EDGES) {
        atomicAdd(&g_deg[src[e]], 1);
        atomicAdd(&g_deg[N_NODES + dst[e]], 1);
    }
}
__global__ void norms_kernel() {
    int i = blockIdx.x * blockDim.x + threadIdx.x;
    if (i < N_NODES) {
        g_norm_src[i] = rsqrtf((float)max(g_deg[i], 1));
        g_norm_dst[i] = rsqrtf((float)max(g_deg[N_NODES + i], 1));
    }
}

// ---- CSR build: block scan of in-degrees -> row_ptr; atomic-cursor fill ----
__global__ void scan_block_kernel() {
    __shared__ int sdata[SCAN_BLK];
    int i = blockIdx.x * SCAN_BLK + threadIdx.x;
    int v = (i < N_NODES) ? g_deg[N_NODES + i] : 0;
    sdata[threadIdx.x] = v;
    __syncthreads();
    for (int off = 1; off < SCAN_BLK; off <<= 1) {
        int t = (threadIdx.x >= off) ? sdata[threadIdx.x - off] : 0;
        __syncthreads();
        sdata[threadIdx.x] += t;
        __syncthreads();
    }
    if (i < N_NODES) g_row_ptr[i + 1] = sdata[threadIdx.x];
    if (threadIdx.x == SCAN_BLK - 1) g_blocksum[blockIdx.x] = sdata[SCAN_BLK - 1];
}
__global__ void scan_tops_kernel() {
    if (threadIdx.x == 0) {
        int acc = 0;
        for (int b = 0; b < NB; b++) { int t = g_blocksum[b]; g_blocksum[b] = acc; acc += t; }
    }
}
// finalizes row_ptr AND seeds cursor
__global__ void scan_add_kernel() {
    int i = blockIdx.x * SCAN_BLK + threadIdx.x;
    if (i < N_NODES) {
        int v = g_row_ptr[i + 1] + g_blocksum[i >> 9];
        g_row_ptr[i + 1] = v;
        if (i + 1 < N_NODES) g_cursor[i + 1] = v;
    }
    if (i == 0) { g_row_ptr[0] = 0; g_cursor[0] = 0; }
}
__global__ void fill_csr_kernel(const int* __restrict__ src, const int* __restrict__ dst) {
    int e = blockIdx.x * blockDim.x + threadIdx.x;
    if (e < N_EDGES) {
        int pos = atomicAdd(&g_cursor[dst[e]], 1);
        g_csr_src[pos] = src[e];
    }
}

__device__ __forceinline__ void bf16_split(float v, __nv_bfloat16& hi, __nv_bfloat16& lo) {
    hi = __float2bfloat16_rn(v);
    lo = __float2bfloat16_rn(v - __bfloat162float(hi));
}
__device__ __forceinline__ uint32_t pack2(__nv_bfloat16 a, __nv_bfloat16 b) {
    __nv_bfloat162 p = __halves2bfloat162(a, b);
    return *(uint32_t*)&p;
}

// B fragment images for mma.m16n8k16 .col B
__global__ void build_Bfrag_kernel(const float* __restrict__ W1, const float* __restrict__ W2,
                                   const float* __restrict__ W3) {
    int t = blockIdx.x * blockDim.x + threadIdx.x;
    if (t >= 3 * 8 * 16 * 32) return;
    int layer = t >> 12;
    int rem = t & 4095;
    int ks = rem >> 9;
    int nt = (rem >> 5) & 15;
    int lane = rem & 31;
    int g = lane >> 2, tig = lane & 3;
    const float* W = (layer == 0) ? W1 : (layer == 1) ? W2 : W3;
    int n = nt * 8 + g;
    int k0 = ks * 16 + 2 * tig;
    float w00 = W[(k0 + 0) * DIM + n];
    float w01 = W[(k0 + 1) * DIM + n];
    float w10 = W[(k0 + 8) * DIM + n];
    float w11 = W[(k0 + 9) * DIM + n];
    __nv_bfloat16 h00, l00, h01, l01, h10, l10, h11, l11;
    bf16_split(w00, h00, l00); bf16_split(w01, h01, l01);
    bf16_split(w10, h10, l10); bf16_split(w11, h11, l11);
    int idx = (layer * 8 + ks) * 16 + nt;
    g_Bfrag[(idx * 2 + 0) * 32 + lane] = make_uint2(pack2(h00, h01), pack2(h10, h11));
    g_Bfrag[(idx * 2 + 1) * 32 + lane] = make_uint2(pack2(l00, l01), pack2(l10, l11));
}

// ---------------- fused layer kernel: aggregate + bf16-split MMA GEMM ----------------
// 512 threads, 2 CTAs/SM. Phase 1: 16 warps x 8 rows CSR segment sum -> smem bf16 hi/lo.
// Phase 2: MMA warp tile 32x32, B fragments loaded per-step (fits 64-reg cap).
// USE_EMB: layer-1 reads emb[batch[s]]*norm_src[s]; else reads hin[s].
// WRITE_MODE 0: hout = relu(...)*norm_src ; 1: hout = relu(...) (final).
#define PADK 136
#define A_IMG_BYTES (128 * PADK * 2)
#define GEMM_SMEM (2 * A_IMG_BYTES)

__device__ __forceinline__ void mma_bf16(float& c0, float& c1, float& c2, float& c3,
                                         uint32_t a0, uint32_t a1, uint32_t a2, uint32_t a3,
                                         uint32_t b0, uint32_t b1) {
    asm volatile(
        "mma.sync.aligned.m16n8k16.row.col.f32.bf16.bf16.f32 "
        "{%0,%1,%2,%3}, {%4,%5,%6,%7}, {%8,%9}, {%0,%1,%2,%3};"
        : "+f"(c0), "+f"(c1), "+f"(c2), "+f"(c3)
        : "r"(a0), "r"(a1), "r"(a2), "r"(a3), "r"(b0), "r"(b1));
}

template <int USE_EMB, int WRITE_MODE>
__global__ __launch_bounds__(512, 2)
void fused_layer_kernel(const float* __restrict__ hin, float* __restrict__ hout,
                        const float* __restrict__ bias, const uint2* __restrict__ Bfrag,
                        const int* __restrict__ batch, const float* __restrict__ emb) {
    extern __shared__ char smem[];
    __nv_bfloat16* sAhi = (__nv_bfloat16*)smem;
    __nv_bfloat16* sAlo = (__nv_bfloat16*)(smem + A_IMG_BYTES);

    int tid = threadIdx.x;
    int wid = tid >> 5, lane = tid & 31;
    int warp_m = wid >> 2, warp_n = wid & 3;      // 4x4 warp grid (MMA phase)
    int g = lane >> 2, tig = lane & 3;
    int row0 = blockIdx.x * 128;

    // ---- phase 1: aggregate 8 rows per warp ----
    #pragma unroll 1
    for (int rr = 0; rr < 8; rr++) {
        int r = wid * 8 + rr;
        int gr = row0 + r;
        float ax = 0.f, ay = 0.f, az = 0.f, aw = 0.f;
        if (gr < N_NODES) {
            int beg = __ldg(g_row_ptr + gr);
            int end = __ldg(g_row_ptr + gr + 1);
            int j = beg;
            for (; j + 3 < end; j += 4) {
                int s0 = __ldg(g_csr_src + j);
                int s1 = __ldg(g_csr_src + j + 1);
                int s2 = __ldg(g_csr_src + j + 2);
                int s3 = __ldg(g_csr_src + j + 3);
                if (USE_EMB) {
                    int b0 = __ldg(batch + s0), b1 = __ldg(batch + s1);
                    int b2 = __ldg(batch + s2), b3 = __ldg(batch + s3);
                    float n0 = __ldg(g_norm_src + s0), n1 = __ldg(g_norm_src + s1);
                    float n2 = __ldg(g_norm_src + s2), n3 = __ldg(g_norm_src + s3);
                    float4 v0 = __ldg((const float4*)(emb + (size_t)b0 * DIM) + lane);
                    float4 v1 = __ldg((const float4*)(emb + (size_t)b1 * DIM) + lane);
                    float4 v2 = __ldg((const float4*)(emb + (size_t)b2 * DIM) + lane);
                    float4 v3 = __ldg((const float4*)(emb + (size_t)b3 * DIM) + lane);
                    ax += v0.x * n0; ay += v0.y * n0; az += v0.z * n0; aw += v0.w * n0;
                    ax += v1.x * n1; ay += v1.y * n1; az += v1.z * n1; aw += v1.w * n1;
                    ax += v2.x * n2; ay += v2.y * n2; az += v2.z * n2; aw += v2.w * n2;
                    ax += v3.x * n3; ay += v3.y * n3; az += v3.z * n3; aw += v3.w * n3;
                } else {
                    float4 v0 = __ldg((const float4*)(hin + (size_t)s0 * DIM) + lane);
                    float4 v1 = __ldg((const float4*)(hin + (size_t)s1 * DIM) + lane);
                    float4 v2 = __ldg((const float4*)(hin + (size_t)s2 * DIM) + lane);
                    float4 v3 = __ldg((const float4*)(hin + (size_t)s3 * DIM) + lane);
                    ax += v0.x; ay += v0.y; az += v0.z; aw += v0.w;
                    ax += v1.x; ay += v1.y; az += v1.z; aw += v1.w;
                    ax += v2.x; ay += v2.y; az += v2.z; aw += v2.w;
                    ax += v3.x; ay += v3.y; az += v3.z; aw += v3.w;
                }
            }
            for (; j < end; j++) {
                int s0 = __ldg(g_csr_src + j);
                if (USE_EMB) {
                    int b0 = __ldg(batch + s0);
                    float n0 = __ldg(g_norm_src + s0);
                    float4 v0 = __ldg((const float4*)(emb + (size_t)b0 * DIM) + lane);
                    ax += v0.x * n0; ay += v0.y * n0; az += v0.z * n0; aw += v0.w * n0;
                } else {
                    float4 v0 = __ldg((const float4*)(hin + (size_t)s0 * DIM) + lane);
                    ax += v0.x; ay += v0.y; az += v0.z; aw += v0.w;
                }
            }
            float nd = __ldg(g_norm_dst + gr);
            ax *= nd; ay *= nd; az *= nd; aw *= nd;
        }
        __nv_bfloat16 h0, l0, h1, l1, h2, l2, h3, l3;
        bf16_split(ax, h0, l0); bf16_split(ay, h1, l1);
        bf16_split(az, h2, l2); bf16_split(aw, h3, l3);
        uint32_t off = (uint32_t)r * PADK + (uint32_t)lane * 4;
        *(uint2*)(sAhi + off) = make_uint2(pack2(h0, h1), pack2(h2, h3));
        *(uint2*)(sAlo + off) = make_uint2(pack2(l0, l1), pack2(l2, l3));
    }
    __syncthreads();

    // ---- phase 2: MMA, warp tile 32 rows x 32 cols ----
    float acc[2][4][4];
    #pragma unroll
    for (int mt = 0; mt < 2; mt++)
        #pragma unroll
        for (int nt = 0; nt < 4; nt++)
            #pragma unroll
            for (int q = 0; q < 4; q++) acc[mt][nt][q] = 0.f;

    const int rbase = warp_m * 32;
    #pragma unroll
    for (int ks = 0; ks < 8; ks++) {
        int kc = ks * 16 + 2 * tig;
        uint32_t ahi[2][4], alo[2][4];
        #pragma unroll
        for (int mt = 0; mt < 2; mt++) {
            int rb = rbase + mt * 16 + g;
            const __nv_bfloat16* ph = sAhi + (uint32_t)rb * PADK + kc;
            const __nv_bfloat16* pl = sAlo + (uint32_t)rb * PADK + kc;
            ahi[mt][0] = *(const uint32_t*)(ph);
            ahi[mt][1] = *(const uint32_t*)(ph + 8 * PADK);
            ahi[mt][2] = *(const uint32_t*)(ph + 8);
            ahi[mt][3] = *(const uint32_t*)(ph + 8 * PADK + 8);
            alo[mt][0] = *(const uint32_t*)(pl);
            alo[mt][1] = *(const uint32_t*)(pl + 8 * PADK);
            alo[mt][2] = *(const uint32_t*)(pl + 8);
            alo[mt][3] = *(const uint32_t*)(pl + 8 * PADK + 8);
        }
        #pragma unroll
        for (int j = 0; j < 4; j++) {
            int ntg = warp_n * 4 + j;
            const uint2* bp = Bfrag + ((size_t)(ks * 16 + ntg) * 2) * 32 + lane;
            uint2 bh = __ldg(bp);
            uint2 bl = __ldg(bp + 32);
            #pragma unroll
            for (int mt = 0; mt < 2; mt++) {
                float* c = acc[mt][j];
                mma_bf16(c[0], c[1], c[2], c[3],
                         ahi[mt][0], ahi[mt][1], ahi[mt][2], ahi[mt][3], bh.x, bh.y);
                mma_bf16(c[0], c[1], c[2], c[3],
                         ahi[mt][0], ahi[mt][1], ahi[mt][2], ahi[mt][3], bl.x, bl.y);
                mma_bf16(c[0], c[1], c[2], c[3],
                         alo[mt][0], alo[mt][1], alo[mt][2], alo[mt][3], bh.x, bh.y);
            }
        }
    }

    // ---- epilogue: bias + relu (+ norm_src fold), write hout ----
    #pragma unroll
    for (int mt = 0; mt < 2; mt++) {
        int ra = row0 + rbase + mt * 16 + g;
        int rb = ra + 8;
        bool va = ra < N_NODES, vb = rb < N_NODES;
        float nsa = 1.f, nsb = 1.f;
        if (WRITE_MODE == 0) {
            if (va) nsa = g_norm_src[ra];
            if (vb) nsb = g_norm_src[rb];
        }
        float* da = hout + (size_t)ra * DIM;
        float* db = hout + (size_t)rb * DIM;
        #pragma unroll
        for (int nt = 0; nt < 4; nt++) {
            int col = warp_n * 32 + nt * 8 + 2 * tig;
            float2 b2 = __ldg((const float2*)(bias + col));
            float* c = acc[mt][nt];
            if (va) {
                float2 o;
                o.x = fmaxf(c[0] + b2.x, 0.f) * nsa;
                o.y = fmaxf(c[1] + b2.y, 0.f) * nsa;
                *(float2*)(da + col) = o;
            }
            if (vb) {
                float2 o;
                o.x = fmaxf(c[2] + b2.x, 0.f) * nsb;
                o.y = fmaxf(c[3] + b2.y, 0.f) * nsb;
                *(float2*)(db + col) = o;
            }
        }
    }
}

// ---------------- launcher ----------------
extern "C" void kernel_launch(void* const* d_in, const int* in_sizes, int n_in,
                              void* d_out, int out_size) {
    const int*   batch = (const int*)  d_in[0];
    const int*   src   = (const int*)  d_in[1];
    const int*   dst   = (const int*)  d_in[2];
    const float* emb   = (const float*)d_in[3];
    const float* W1    = (const float*)d_in[4];
    const float* b1    = (const float*)d_in[5];
    const float* W2    = (const float*)d_in[6];
    const float* b2    = (const float*)d_in[7];
    const float* W3    = (const float*)d_in[8];
    const float* b3    = (const float*)d_in[9];
    float* out = (float*)d_out;
    (void)in_sizes; (void)n_in; (void)out_size;

    cudaFuncSetAttribute(fused_layer_kernel<1, 0>, cudaFuncAttributeMaxDynamicSharedMemorySize, GEMM_SMEM);
    cudaFuncSetAttribute(fused_layer_kernel<0, 0>, cudaFuncAttributeMaxDynamicSharedMemorySize, GEMM_SMEM);
    cudaFuncSetAttribute(fused_layer_kernel<0, 1>, cudaFuncAttributeMaxDynamicSharedMemorySize, GEMM_SMEM);

    void* bf_ptr = nullptr;  cudaGetSymbolAddress(&bf_ptr, g_Bfrag);
    void* hs_ptr = nullptr;  cudaGetSymbolAddress(&hs_ptr, g_hs);
    void* hs2_ptr = nullptr; cudaGetSymbolAddress(&hs2_ptr, g_hs2);
    const uint2* Bf = (const uint2*)bf_ptr;
    float* hs  = (float*)hs_ptr;
    float* hs2 = (float*)hs2_ptr;
    const size_t BF_LAYER = 8 * 16 * 2 * 32;

    // degrees + norms + W fragment images
    zero_deg_kernel<<<(2 * N_NODES + 255) / 256, 256>>>();
    count_deg_kernel<<<(N_EDGES + 255) / 256, 256>>>(src, dst);
    norms_kernel<<<(N_NODES + 255) / 256, 256>>>();
    build_Bfrag_kernel<<<(3 * 8 * 16 * 32 + 255) / 256, 256>>>(W1, W2, W3);

    // CSR by dst (cursor seeded inside scan_add)
    scan_block_kernel<<<NB, SCAN_BLK>>>();
    scan_tops_kernel<<<1, 32>>>();
    scan_add_kernel<<<NB, SCAN_BLK>>>();
    fill_csr_kernel<<<(N_EDGES + 255) / 256, 256>>>(src, dst);

    const int blocks = (N_NODES + 127) / 128;

    // layer 1: (emb,batch) -> hs2 ; layer 2: hs2 -> hs ; layer 3: hs -> out
    fused_layer_kernel<1, 0><<<blocks, 512, GEMM_SMEM>>>(nullptr, hs2, b1, Bf + 0 * BF_LAYER, batch, emb);
    fused_layer_kernel<0, 0><<<blocks, 512, GEMM_SMEM>>>(hs2, hs, b2, Bf + 1 * BF_LAYER, nullptr, nullptr);
    fused_layer_kernel<0, 1><<<blocks, 512, GEMM_SMEM>>>(hs, out, b3, Bf + 2 * BF_LAYER, nullptr, nullptr);
}

// round 12
// speedup vs baseline: 1.2504x; 1.2504x over previous
#include <cuda_runtime.h>
#include <cuda_bf16.h>
#include <cuda_fp16.h>
#include <cstdint>

#define N_NODES 50000
#define N_EDGES 800000
#define DIM 128
#define VOCAB 50000
#define SCAN_BLK 512
#define NB ((N_NODES + SCAN_BLK - 1) / SCAN_BLK)   // 98

// ---------------- device scratch (static, allocation-free, zero-initialized) ----
__device__ __half g_h16a[(size_t)N_NODES * DIM];   // feature ping (fp16)
__device__ __half g_h16b[(size_t)N_NODES * DIM];   // feature pong (fp16)
__device__ __half g_emb16[(size_t)VOCAB * DIM];    // fp16 copy of emb table
__device__ float  g_agg[(size_t)N_NODES * DIM];    // normalized aggregate (fp32)
__device__ float  g_norm_src[N_NODES];
__device__ float  g_norm_dst[N_NODES];
__device__ int    g_deg[2 * N_NODES];
__device__ int    g_row_ptr[N_NODES + 1];          // CSR by dst
__device__ int    g_cursor[N_NODES];
__device__ int    g_blocksum[NB];
__device__ int    g_csr_src[N_EDGES];
// W fragment images: [layer][kstep(8)][ntile(16)][img(2)][lane(32)] of uint2
__device__ uint2  g_Bfrag[3 * 8 * 16 * 2 * 32];

// ---------------- prep kernels ----------------
__global__ void zero_deg_kernel() {
    int i = blockIdx.x * blockDim.x + threadIdx.x;
    if (i < 2 * N_NODES) g_deg[i] = 0;
}
__global__ void count_deg_kernel(const int* __restrict__ src, const int* __restrict__ dst) {
    int e = blockIdx.x * blockDim.x + threadIdx.x;
    if (e < N_EDGES) {
        atomicAdd(&g_deg[src[e]], 1);
        atomicAdd(&g_deg[N_NODES + dst[e]], 1);
    }
}
__global__ void norms_kernel() {
    int i = blockIdx.x * blockDim.x + threadIdx.x;
    if (i < N_NODES) {
        g_norm_src[i] = rsqrtf((float)max(g_deg[i], 1));
        g_norm_dst[i] = rsqrtf((float)max(g_deg[N_NODES + i], 1));
    }
}
// emb -> fp16 copy (4 elems/thread)
__global__ void conv_emb_kernel(const float* __restrict__ emb) {
    int i = blockIdx.x * blockDim.x + threadIdx.x;
    if (i < VOCAB * DIM / 4) {
        float4 v = __ldg((const float4*)emb + i);
        __half2 a = __floats2half2_rn(v.x, v.y);
        __half2 b = __floats2half2_rn(v.z, v.w);
        ((uint2*)g_emb16)[i] = make_uint2(*(uint32_t*)&a, *(uint32_t*)&b);
    }
}

// ---- CSR build ----
__global__ void scan_block_kernel() {
    __shared__ int sdata[SCAN_BLK];
    int i = blockIdx.x * SCAN_BLK + threadIdx.x;
    int v = (i < N_NODES) ? g_deg[N_NODES + i] : 0;
    sdata[threadIdx.x] = v;
    __syncthreads();
    for (int off = 1; off < SCAN_BLK; off <<= 1) {
        int t = (threadIdx.x >= off) ? sdata[threadIdx.x - off] : 0;
        __syncthreads();
        sdata[threadIdx.x] += t;
        __syncthreads();
    }
    if (i < N_NODES) g_row_ptr[i + 1] = sdata[threadIdx.x];
    if (threadIdx.x == SCAN_BLK - 1) g_blocksum[blockIdx.x] = sdata[SCAN_BLK - 1];
}
__global__ void scan_tops_kernel() {
    if (threadIdx.x == 0) {
        int acc = 0;
        for (int b = 0; b < NB; b++) { int t = g_blocksum[b]; g_blocksum[b] = acc; acc += t; }
    }
}
__global__ void scan_add_kernel() {
    int i = blockIdx.x * SCAN_BLK + threadIdx.x;
    if (i < N_NODES) {
        int v = g_row_ptr[i + 1] + g_blocksum[i >> 9];
        g_row_ptr[i + 1] = v;
        if (i + 1 < N_NODES) g_cursor[i + 1] = v;
    }
    if (i == 0) { g_row_ptr[0] = 0; g_cursor[0] = 0; }
}
__global__ void fill_csr_kernel(const int* __restrict__ src, const int* __restrict__ dst) {
    int e = blockIdx.x * blockDim.x + threadIdx.x;
    if (e < N_EDGES) {
        int pos = atomicAdd(&g_cursor[dst[e]], 1);
        g_csr_src[pos] = src[e];
    }
}

__device__ __forceinline__ void bf16_split(float v, __nv_bfloat16& hi, __nv_bfloat16& lo) {
    hi = __float2bfloat16_rn(v);
    lo = __float2bfloat16_rn(v - __bfloat162float(hi));
}
__device__ __forceinline__ uint32_t pack2(__nv_bfloat16 a, __nv_bfloat16 b) {
    __nv_bfloat162 p = __halves2bfloat162(a, b);
    return *(uint32_t*)&p;
}

// B fragment images for mma.m16n8k16 .col B
__global__ void build_Bfrag_kernel(const float* __restrict__ W1, const float* __restrict__ W2,
                                   const float* __restrict__ W3) {
    int t = blockIdx.x * blockDim.x + threadIdx.x;
    if (t >= 3 * 8 * 16 * 32) return;
    int layer = t >> 12;
    int rem = t & 4095;
    int ks = rem >> 9;
    int nt = (rem >> 5) & 15;
    int lane = rem & 31;
    int g = lane >> 2, tig = lane & 3;
    const float* W = (layer == 0) ? W1 : (layer == 1) ? W2 : W3;
    int n = nt * 8 + g;
    int k0 = ks * 16 + 2 * tig;
    float w00 = W[(k0 + 0) * DIM + n];
    float w01 = W[(k0 + 1) * DIM + n];
    float w10 = W[(k0 + 8) * DIM + n];
    float w11 = W[(k0 + 9) * DIM + n];
    __nv_bfloat16 h00, l00, h01, l01, h10, l10, h11, l11;
    bf16_split(w00, h00, l00); bf16_split(w01, h01, l01);
    bf16_split(w10, h10, l10); bf16_split(w11, h11, l11);
    int idx = (layer * 8 + ks) * 16 + nt;
    g_Bfrag[(idx * 2 + 0) * 32 + lane] = make_uint2(pack2(h00, h01), pack2(h10, h11));
    g_Bfrag[(idx * 2 + 1) * 32 + lane] = make_uint2(pack2(l00, l01), pack2(l10, l11));
}

// ---------------- aggregation kernels (fp16 features, fp32 accumulation) ----------------
__device__ __forceinline__ void acc_h4(float& ax, float& ay, float& az, float& aw,
                                       uint2 u, float s) {
    __half2 p0 = *(__half2*)&u.x;
    __half2 p1 = *(__half2*)&u.y;
    float2 f0 = __half22float2(p0);
    float2 f1 = __half22float2(p1);
    ax += f0.x * s; ay += f0.y * s; az += f1.x * s; aw += f1.y * s;
}

// Layer 1: g_agg[r] = norm_dst[r] * sum_e emb16[batch[src_e]] * norm_src[src_e]
__global__ __launch_bounds__(256)
void aggregate_emb_kernel(const int* __restrict__ batch) {
    int t = blockIdx.x * blockDim.x + threadIdx.x;
    int gr = t >> 5;
    int lane = t & 31;
    if (gr >= N_NODES) return;

    int beg = __ldg(g_row_ptr + gr);
    int end = __ldg(g_row_ptr + gr + 1);
    float ax = 0.f, ay = 0.f, az = 0.f, aw = 0.f;
    int j = beg;
    for (; j + 3 < end; j += 4) {
        int s0 = __ldg(g_csr_src + j);
        int s1 = __ldg(g_csr_src + j + 1);
        int s2 = __ldg(g_csr_src + j + 2);
        int s3 = __ldg(g_csr_src + j + 3);
        int b0 = __ldg(batch + s0), b1 = __ldg(batch + s1);
        int b2 = __ldg(batch + s2), b3 = __ldg(batch + s3);
        float n0 = __ldg(g_norm_src + s0), n1 = __ldg(g_norm_src + s1);
        float n2 = __ldg(g_norm_src + s2), n3 = __ldg(g_norm_src + s3);
        uint2 u0 = __ldg((const uint2*)(g_emb16 + (size_t)b0 * DIM) + lane);
        uint2 u1 = __ldg((const uint2*)(g_emb16 + (size_t)b1 * DIM) + lane);
        uint2 u2 = __ldg((const uint2*)(g_emb16 + (size_t)b2 * DIM) + lane);
        uint2 u3 = __ldg((const uint2*)(g_emb16 + (size_t)b3 * DIM) + lane);
        acc_h4(ax, ay, az, aw, u0, n0);
        acc_h4(ax, ay, az, aw, u1, n1);
        acc_h4(ax, ay, az, aw, u2, n2);
        acc_h4(ax, ay, az, aw, u3, n3);
    }
    for (; j < end; j++) {
        int s0 = __ldg(g_csr_src + j);
        int b0 = __ldg(batch + s0);
        float n0 = __ldg(g_norm_src + s0);
        uint2 u0 = __ldg((const uint2*)(g_emb16 + (size_t)b0 * DIM) + lane);
        acc_h4(ax, ay, az, aw, u0, n0);
    }
    float nd = __ldg(g_norm_dst + gr);
    ((float4*)(g_agg + (size_t)gr * DIM))[lane] = make_float4(ax * nd, ay * nd, az * nd, aw * nd);
}

// Layers 2-3: g_agg[r] = norm_dst[r] * sum_e hin16[src_e]
__global__ __launch_bounds__(256)
void aggregate_kernel(const __half* __restrict__ hin) {
    int t = blockIdx.x * blockDim.x + threadIdx.x;
    int gr = t >> 5;
    int lane = t & 31;
    if (gr >= N_NODES) return;

    int beg = __ldg(g_row_ptr + gr);
    int end = __ldg(g_row_ptr + gr + 1);
    float ax = 0.f, ay = 0.f, az = 0.f, aw = 0.f;
    int j = beg;
    for (; j + 3 < end; j += 4) {
        int s0 = __ldg(g_csr_src + j);
        int s1 = __ldg(g_csr_src + j + 1);
        int s2 = __ldg(g_csr_src + j + 2);
        int s3 = __ldg(g_csr_src + j + 3);
        uint2 u0 = __ldg((const uint2*)(hin + (size_t)s0 * DIM) + lane);
        uint2 u1 = __ldg((const uint2*)(hin + (size_t)s1 * DIM) + lane);
        uint2 u2 = __ldg((const uint2*)(hin + (size_t)s2 * DIM) + lane);
        uint2 u3 = __ldg((const uint2*)(hin + (size_t)s3 * DIM) + lane);
        acc_h4(ax, ay, az, aw, u0, 1.f);
        acc_h4(ax, ay, az, aw, u1, 1.f);
        acc_h4(ax, ay, az, aw, u2, 1.f);
        acc_h4(ax, ay, az, aw, u3, 1.f);
    }
    for (; j < end; j++) {
        int s0 = __ldg(g_csr_src + j);
        uint2 u0 = __ldg((const uint2*)(hin + (size_t)s0 * DIM) + lane);
        acc_h4(ax, ay, az, aw, u0, 1.f);
    }
    float nd = __ldg(g_norm_dst + gr);
    ((float4*)(g_agg + (size_t)gr * DIM))[lane] = make_float4(ax * nd, ay * nd, az * nd, aw * nd);
}

// ---------------- bf16-split mma GEMM (R10 structure, 512 thr, 4x4 warps) ----------------
// WRITE_MODE 0: hout16 = half(relu(...)*norm_src) ; 1: outf = relu(...) (final fp32)
#define PADK 136
#define A_IMG_BYTES (128 * PADK * 2)
#define GEMM_SMEM (2 * A_IMG_BYTES)

__device__ __forceinline__ void mma_bf16(float& c0, float& c1, float& c2, float& c3,
                                         uint32_t a0, uint32_t a1, uint32_t a2, uint32_t a3,
                                         uint32_t b0, uint32_t b1) {
    asm volatile(
        "mma.sync.aligned.m16n8k16.row.col.f32.bf16.bf16.f32 "
        "{%0,%1,%2,%3}, {%4,%5,%6,%7}, {%8,%9}, {%0,%1,%2,%3};"
        : "+f"(c0), "+f"(c1), "+f"(c2), "+f"(c3)
        : "r"(a0), "r"(a1), "r"(a2), "r"(a3), "r"(b0), "r"(b1));
}

template <int WRITE_MODE>
__global__ __launch_bounds__(512, 2)
void mma_gemm_kernel(__half* __restrict__ hout16, float* __restrict__ outf,
                     const float* __restrict__ bias, const uint2* __restrict__ Bfrag) {
    extern __shared__ char smem[];
    __nv_bfloat16* sAhi = (__nv_bfloat16*)smem;
    __nv_bfloat16* sAlo = (__nv_bfloat16*)(smem + A_IMG_BYTES);

    int tid = threadIdx.x;
    int wid = tid >> 5, lane = tid & 31;
    int warp_m = wid >> 2, warp_n = wid & 3;      // 4x4 warp grid
    int g = lane >> 2, tig = lane & 3;
    int row0 = blockIdx.x * 128;

    // ---- load A tile (coalesced stream from g_agg), bf16 split into smem ----
    #pragma unroll
    for (int it = 0; it < 8; it++) {
        int i = tid + it * 512;
        int r = i >> 5, c4 = i & 31;
        int gr = row0 + r;
        float4 v = make_float4(0.f, 0.f, 0.f, 0.f);
        if (gr < N_NODES)
            v = ((const float4*)(g_agg + (size_t)gr * DIM))[c4];
        __nv_bfloat16 h0, l0, h1, l1, h2, l2, h3, l3;
        bf16_split(v.x, h0, l0); bf16_split(v.y, h1, l1);
        bf16_split(v.z, h2, l2); bf16_split(v.w, h3, l3);
        uint32_t off = (uint32_t)r * PADK + (uint32_t)c4 * 4;
        *(uint2*)(sAhi + off) = make_uint2(pack2(h0, h1), pack2(h2, h3));
        *(uint2*)(sAlo + off) = make_uint2(pack2(l0, l1), pack2(l2, l3));
    }
    __syncthreads();

    // ---- MMA: warp tile 32 rows x 32 cols ----
    float acc[2][4][4];
    #pragma unroll
    for (int mt = 0; mt < 2; mt++)
        #pragma unroll
        for (int nt = 0; nt < 4; nt++)
            #pragma unroll
            for (int q = 0; q < 4; q++) acc[mt][nt][q] = 0.f;

    const int rbase = warp_m * 32;
    #pragma unroll
    for (int ks = 0; ks < 8; ks++) {
        int kc = ks * 16 + 2 * tig;
        uint32_t ahi[2][4], alo[2][4];
        #pragma unroll
        for (int mt = 0; mt < 2; mt++) {
            int rb = rbase + mt * 16 + g;
            const __nv_bfloat16* ph = sAhi + (uint32_t)rb * PADK + kc;
            const __nv_bfloat16* pl = sAlo + (uint32_t)rb * PADK + kc;
            ahi[mt][0] = *(const uint32_t*)(ph);
            ahi[mt][1] = *(const uint32_t*)(ph + 8 * PADK);
            ahi[mt][2] = *(const uint32_t*)(ph + 8);
            ahi[mt][3] = *(const uint32_t*)(ph + 8 * PADK + 8);
            alo[mt][0] = *(const uint32_t*)(pl);
            alo[mt][1] = *(const uint32_t*)(pl + 8 * PADK);
            alo[mt][2] = *(const uint32_t*)(pl + 8);
            alo[mt][3] = *(const uint32_t*)(pl + 8 * PADK + 8);
        }
        uint2 bh[4], bl[4];
        #pragma unroll
        for (int j = 0; j < 4; j++) {
            int ntg = warp_n * 4 + j;
            const uint2* bp = Bfrag + ((size_t)(ks * 16 + ntg) * 2) * 32 + lane;
            bh[j] = __ldg(bp);
            bl[j] = __ldg(bp + 32);
        }
        #pragma unroll
        for (int j = 0; j < 4; j++) {
            #pragma unroll
            for (int mt = 0; mt < 2; mt++) {
                float* c = acc[mt][j];
                mma_bf16(c[0], c[1], c[2], c[3],
                         ahi[mt][0], ahi[mt][1], ahi[mt][2], ahi[mt][3], bh[j].x, bh[j].y);
                mma_bf16(c[0], c[1], c[2], c[3],
                         ahi[mt][0], ahi[mt][1], ahi[mt][2], ahi[mt][3], bl[j].x, bl[j].y);
                mma_bf16(c[0], c[1], c[2], c[3],
                         alo[mt][0], alo[mt][1], alo[mt][2], alo[mt][3], bh[j].x, bh[j].y);
            }
        }
    }

    // ---- epilogue: bias + relu (+ norm_src fold), write fp16 (or final fp32) ----
    #pragma unroll
    for (int mt = 0; mt < 2; mt++) {
        int ra = row0 + rbase + mt * 16 + g;
        int rb = ra + 8;
        bool va = ra < N_NODES, vb = rb < N_NODES;
        float nsa = 1.f, nsb = 1.f;
        if (WRITE_MODE == 0) {
            if (va) nsa = g_norm_src[ra];
            if (vb) nsb = g_norm_src[rb];
        }
        #pragma unroll
        for (int nt = 0; nt < 4; nt++) {
            int col = warp_n * 32 + nt * 8 + 2 * tig;
            float2 b2 = __ldg((const float2*)(bias + col));
            float* c = acc[mt][nt];
            if (WRITE_MODE == 0) {
                if (va) {
                    __half2 o = __floats2half2_rn(fmaxf(c[0] + b2.x, 0.f) * nsa,
                                                  fmaxf(c[1] + b2.y, 0.f) * nsa);
                    *(__half2*)(hout16 + (size_t)ra * DIM + col) = o;
                }
                if (vb) {
                    __half2 o = __floats2half2_rn(fmaxf(c[2] + b2.x, 0.f) * nsb,
                                                  fmaxf(c[3] + b2.y, 0.f) * nsb);
                    *(__half2*)(hout16 + (size_t)rb * DIM + col) = o;
                }
            } else {
                if (va) {
                    float2 o;
                    o.x = fmaxf(c[0] + b2.x, 0.f);
                    o.y = fmaxf(c[1] + b2.y, 0.f);
                    *(float2*)(outf + (size_t)ra * DIM + col) = o;
                }
                if (vb) {
                    float2 o;
                    o.x = fmaxf(c[2] + b2.x, 0.f);
                    o.y = fmaxf(c[3] + b2.y, 0.f);
                    *(float2*)(outf + (size_t)rb * DIM + col) = o;
                }
            }
        }
    }
}

// ---------------- launcher ----------------
extern "C" void kernel_launch(void* const* d_in, const int* in_sizes, int n_in,
                              void* d_out, int out_size) {
    const int*   batch = (const int*)  d_in[0];
    const int*   src   = (const int*)  d_in[1];
    const int*   dst   = (const int*)  d_in[2];
    const float* emb   = (const float*)d_in[3];
    const float* W1    = (const float*)d_in[4];
    const float* b1    = (const float*)d_in[5];
    const float* W2    = (const float*)d_in[6];
    const float* b2    = (const float*)d_in[7];
    const float* W3    = (const float*)d_in[8];
    const float* b3    = (const float*)d_in[9];
    float* out = (float*)d_out;
    (void)in_sizes; (void)n_in; (void)out_size;

    cudaFuncSetAttribute(mma_gemm_kernel<0>, cudaFuncAttributeMaxDynamicSharedMemorySize, GEMM_SMEM);
    cudaFuncSetAttribute(mma_gemm_kernel<1>, cudaFuncAttributeMaxDynamicSharedMemorySize, GEMM_SMEM);

    void* bf_ptr = nullptr;  cudaGetSymbolAddress(&bf_ptr, g_Bfrag);
    void* ha_ptr = nullptr;  cudaGetSymbolAddress(&ha_ptr, g_h16a);
    void* hb_ptr = nullptr;  cudaGetSymbolAddress(&hb_ptr, g_h16b);
    const uint2* Bf = (const uint2*)bf_ptr;
    __half* h16a = (__half*)ha_ptr;
    __half* h16b = (__half*)hb_ptr;
    const size_t BF_LAYER = 8 * 16 * 2 * 32;

    // degrees + norms + W fragment images + emb16
    zero_deg_kernel<<<(2 * N_NODES + 255) / 256, 256>>>();
    count_deg_kernel<<<(N_EDGES + 255) / 256, 256>>>(src, dst);
    norms_kernel<<<(N_NODES + 255) / 256, 256>>>();
    build_Bfrag_kernel<<<(3 * 8 * 16 * 32 + 255) / 256, 256>>>(W1, W2, W3);
    conv_emb_kernel<<<(VOCAB * DIM / 4 + 255) / 256, 256>>>(emb);

    // CSR by dst (cursor seeded inside scan_add)
    scan_block_kernel<<<NB, SCAN_BLK>>>();
    scan_tops_kernel<<<1, 32>>>();
    scan_add_kernel<<<NB, SCAN_BLK>>>();
    fill_csr_kernel<<<(N_EDGES + 255) / 256, 256>>>(src, dst);

    const int agg_blocks = (N_NODES * 32 + 255) / 256;
    const int gemm_blocks = (N_NODES + 127) / 128;

    // layer 1: (emb16, batch) -> agg -> h16a
    aggregate_emb_kernel<<<agg_blocks, 256>>>(batch);
    mma_gemm_kernel<0><<<gemm_blocks, 512, GEMM_SMEM>>>(h16a, nullptr, b1, Bf + 0 * BF_LAYER);
    // layer 2: h16a -> agg -> h16b
    aggregate_kernel<<<agg_blocks, 256>>>(h16a);
    mma_gemm_kernel<0><<<gemm_blocks, 512, GEMM_SMEM>>>(h16b, nullptr, b2, Bf + 1 * BF_LAYER);
    // layer 3: h16b -> agg -> out (final fp32)
    aggregate_kernel<<<agg_blocks, 256>>>(h16b);
    mma_gemm_kernel<1><<<gemm_blocks, 512, GEMM_SMEM>>>(nullptr, out, b3, Bf + 2 * BF_LAYER);
}

// round 13
// speedup vs baseline: 1.3041x; 1.0430x over previous
#include <cuda_runtime.h>
#include <cuda_bf16.h>
#include <cuda_fp16.h>
#include <cstdint>

#define N_NODES 50000
#define N_EDGES 800000
#define DIM 128
#define VOCAB 50000
#define SCAN_BLK 512
#define NB ((N_NODES + SCAN_BLK - 1) / SCAN_BLK)   // 98

// ---------------- device scratch (static, allocation-free, zero-initialized) ----
__device__ __half g_h16a[(size_t)N_NODES * DIM];   // feature ping (fp16)
__device__ __half g_h16b[(size_t)N_NODES * DIM];   // feature pong (fp16)
__device__ __half g_emb16[(size_t)VOCAB * DIM];    // fp16 copy of emb table
__device__ float  g_agg[(size_t)N_NODES * DIM];    // normalized aggregate (fp32)
__device__ float  g_norm_src[N_NODES];
__device__ float  g_norm_dst[N_NODES];
__device__ int    g_deg[2 * N_NODES];
__device__ int    g_row_ptr[N_NODES + 1];          // CSR by dst
__device__ int    g_cursor[N_NODES];
__device__ int    g_blocksum[NB];
__device__ int    g_csr_src[N_EDGES];
// W fragment images: [layer][kstep(8)][ntile(16)][img(2)][lane(32)] of uint2
__device__ uint2  g_Bfrag[3 * 8 * 16 * 2 * 32];

__device__ __forceinline__ void bf16_split(float v, __nv_bfloat16& hi, __nv_bfloat16& lo) {
    hi = __float2bfloat16_rn(v);
    lo = __float2bfloat16_rn(v - __bfloat162float(hi));
}
__device__ __forceinline__ uint32_t pack2(__nv_bfloat16 a, __nv_bfloat16 b) {
    __nv_bfloat162 p = __halves2bfloat162(a, b);
    return *(uint32_t*)&p;
}

// ---------------- merged init: conv_emb + zero_deg + build_Bfrag ----------------
// grid = VOCAB*DIM/4 threads (1.6M); sub-jobs gated by thread index.
__global__ void init_kernel(const float* __restrict__ emb,
                            const float* __restrict__ W1, const float* __restrict__ W2,
                            const float* __restrict__ W3) {
    int i = blockIdx.x * blockDim.x + threadIdx.x;

    // job 1: emb -> fp16 copy (4 elems/thread)
    if (i < VOCAB * DIM / 4) {
        float4 v = __ldg((const float4*)emb + i);
        __half2 a = __floats2half2_rn(v.x, v.y);
        __half2 b = __floats2half2_rn(v.z, v.w);
        ((uint2*)g_emb16)[i] = make_uint2(*(uint32_t*)&a, *(uint32_t*)&b);
    }
    // job 2: zero degree counters
    if (i < 2 * N_NODES) g_deg[i] = 0;
    // job 3: B fragment images for mma.m16n8k16 .col B
    if (i < 3 * 8 * 16 * 32) {
        int layer = i >> 12;
        int rem = i & 4095;
        int ks = rem >> 9;
        int nt = (rem >> 5) & 15;
        int lane = rem & 31;
        int g = lane >> 2, tig = lane & 3;
        const float* W = (layer == 0) ? W1 : (layer == 1) ? W2 : W3;
        int n = nt * 8 + g;
        int k0 = ks * 16 + 2 * tig;
        float w00 = W[(k0 + 0) * DIM + n];
        float w01 = W[(k0 + 1) * DIM + n];
        float w10 = W[(k0 + 8) * DIM + n];
        float w11 = W[(k0 + 9) * DIM + n];
        __nv_bfloat16 h00, l00, h01, l01, h10, l10, h11, l11;
        bf16_split(w00, h00, l00); bf16_split(w01, h01, l01);
        bf16_split(w10, h10, l10); bf16_split(w11, h11, l11);
        int idx = (layer * 8 + ks) * 16 + nt;
        g_Bfrag[(idx * 2 + 0) * 32 + lane] = make_uint2(pack2(h00, h01), pack2(h10, h11));
        g_Bfrag[(idx * 2 + 1) * 32 + lane] = make_uint2(pack2(l00, l01), pack2(l10, l11));
    }
}

__global__ void count_deg_kernel(const int* __restrict__ src, const int* __restrict__ dst) {
    int e = blockIdx.x * blockDim.x + threadIdx.x;
    if (e < N_EDGES) {
        atomicAdd(&g_deg[src[e]], 1);
        atomicAdd(&g_deg[N_NODES + dst[e]], 1);
    }
}

// ---- scan_block + norms merged (both consume g_deg) ----
__global__ void scan_block_norms_kernel() {
    __shared__ int sdata[SCAN_BLK];
    int i = blockIdx.x * SCAN_BLK + threadIdx.x;
    int v = 0;
    if (i < N_NODES) {
        int din = g_deg[N_NODES + i];
        v = din;
        g_norm_src[i] = rsqrtf((float)max(g_deg[i], 1));
        g_norm_dst[i] = rsqrtf((float)max(din, 1));
    }
    sdata[threadIdx.x] = v;
    __syncthreads();
    for (int off = 1; off < SCAN_BLK; off <<= 1) {
        int t = (threadIdx.x >= off) ? sdata[threadIdx.x - off] : 0;
        __syncthreads();
        sdata[threadIdx.x] += t;
        __syncthreads();
    }
    if (i < N_NODES) g_row_ptr[i + 1] = sdata[threadIdx.x];
    if (threadIdx.x == SCAN_BLK - 1) g_blocksum[blockIdx.x] = sdata[SCAN_BLK - 1];
}

// parallel exclusive scan over NB=98 block sums (one 128-thread block)
__global__ void scan_tops_kernel() {
    __shared__ int s[128];
    int tid = threadIdx.x;
    int v = (tid < NB) ? g_blocksum[tid] : 0;
    s[tid] = v;
    __syncthreads();
    for (int off = 1; off < 128; off <<= 1) {
        int t = (tid >= off) ? s[tid - off] : 0;
        __syncthreads();
        s[tid] += t;
        __syncthreads();
    }
    if (tid < NB) g_blocksum[tid] = s[tid] - v;   // exclusive
}

__global__ void scan_add_kernel() {
    int i = blockIdx.x * SCAN_BLK + threadIdx.x;
    if (i < N_NODES) {
        int v = g_row_ptr[i + 1] + g_blocksum[i >> 9];
        g_row_ptr[i + 1] = v;
        if (i + 1 < N_NODES) g_cursor[i + 1] = v;
    }
    if (i == 0) { g_row_ptr[0] = 0; g_cursor[0] = 0; }
}
__global__ void fill_csr_kernel(const int* __restrict__ src, const int* __restrict__ dst) {
    int e = blockIdx.x * blockDim.x + threadIdx.x;
    if (e < N_EDGES) {
        int pos = atomicAdd(&g_cursor[dst[e]], 1);
        g_csr_src[pos] = src[e];
    }
}

// ---------------- aggregation kernels (fp16 features, fp32 accumulation) ----------------
__device__ __forceinline__ void acc_h4(float& ax, float& ay, float& az, float& aw,
                                       uint2 u, float s) {
    __half2 p0 = *(__half2*)&u.x;
    __half2 p1 = *(__half2*)&u.y;
    float2 f0 = __half22float2(p0);
    float2 f1 = __half22float2(p1);
    ax += f0.x * s; ay += f0.y * s; az += f1.x * s; aw += f1.y * s;
}

// Layer 1: g_agg[r] = norm_dst[r] * sum_e emb16[batch[src_e]] * norm_src[src_e]
__global__ __launch_bounds__(256)
void aggregate_emb_kernel(const int* __restrict__ batch) {
    int t = blockIdx.x * blockDim.x + threadIdx.x;
    int gr = t >> 5;
    int lane = t & 31;
    if (gr >= N_NODES) return;

    int beg = __ldg(g_row_ptr + gr);
    int end = __ldg(g_row_ptr + gr + 1);
    float ax = 0.f, ay = 0.f, az = 0.f, aw = 0.f;
    int j = beg;
    for (; j + 3 < end; j += 4) {
        int s0 = __ldg(g_csr_src + j);
        int s1 = __ldg(g_csr_src + j + 1);
        int s2 = __ldg(g_csr_src + j + 2);
        int s3 = __ldg(g_csr_src + j + 3);
        int b0 = __ldg(batch + s0), b1 = __ldg(batch + s1);
        int b2 = __ldg(batch + s2), b3 = __ldg(batch + s3);
        float n0 = __ldg(g_norm_src + s0), n1 = __ldg(g_norm_src + s1);
        float n2 = __ldg(g_norm_src + s2), n3 = __ldg(g_norm_src + s3);
        uint2 u0 = __ldg((const uint2*)(g_emb16 + (size_t)b0 * DIM) + lane);
        uint2 u1 = __ldg((const uint2*)(g_emb16 + (size_t)b1 * DIM) + lane);
        uint2 u2 = __ldg((const uint2*)(g_emb16 + (size_t)b2 * DIM) + lane);
        uint2 u3 = __ldg((const uint2*)(g_emb16 + (size_t)b3 * DIM) + lane);
        acc_h4(ax, ay, az, aw, u0, n0);
        acc_h4(ax, ay, az, aw, u1, n1);
        acc_h4(ax, ay, az, aw, u2, n2);
        acc_h4(ax, ay, az, aw, u3, n3);
    }
    for (; j < end; j++) {
        int s0 = __ldg(g_csr_src + j);
        int b0 = __ldg(batch + s0);
        float n0 = __ldg(g_norm_src + s0);
        uint2 u0 = __ldg((const uint2*)(g_emb16 + (size_t)b0 * DIM) + lane);
        acc_h4(ax, ay, az, aw, u0, n0);
    }
    float nd = __ldg(g_norm_dst + gr);
    ((float4*)(g_agg + (size_t)gr * DIM))[lane] = make_float4(ax * nd, ay * nd, az * nd, aw * nd);
}

// Layers 2-3: g_agg[r] = norm_dst[r] * sum_e hin16[src_e]
__global__ __launch_bounds__(256)
void aggregate_kernel(const __half* __restrict__ hin) {
    int t = blockIdx.x * blockDim.x + threadIdx.x;
    int gr = t >> 5;
    int lane = t & 31;
    if (gr >= N_NODES) return;

    int beg = __ldg(g_row_ptr + gr);
    int end = __ldg(g_row_ptr + gr + 1);
    float ax = 0.f, ay = 0.f, az = 0.f, aw = 0.f;
    int j = beg;
    for (; j + 3 < end; j += 4) {
        int s0 = __ldg(g_csr_src + j);
        int s1 = __ldg(g_csr_src + j + 1);
        int s2 = __ldg(g_csr_src + j + 2);
        int s3 = __ldg(g_csr_src + j + 3);
        uint2 u0 = __ldg((const uint2*)(hin + (size_t)s0 * DIM) + lane);
        uint2 u1 = __ldg((const uint2*)(hin + (size_t)s1 * DIM) + lane);
        uint2 u2 = __ldg((const uint2*)(hin + (size_t)s2 * DIM) + lane);
        uint2 u3 = __ldg((const uint2*)(hin + (size_t)s3 * DIM) + lane);
        acc_h4(ax, ay, az, aw, u0, 1.f);
        acc_h4(ax, ay, az, aw, u1, 1.f);
        acc_h4(ax, ay, az, aw, u2, 1.f);
        acc_h4(ax, ay, az, aw, u3, 1.f);
    }
    for (; j < end; j++) {
        int s0 = __ldg(g_csr_src + j);
        uint2 u0 = __ldg((const uint2*)(hin + (size_t)s0 * DIM) + lane);
        acc_h4(ax, ay, az, aw, u0, 1.f);
    }
    float nd = __ldg(g_norm_dst + gr);
    ((float4*)(g_agg + (size_t)gr * DIM))[lane] = make_float4(ax * nd, ay * nd, az * nd, aw * nd);
}

// ---------------- bf16-split mma GEMM (512 thr, 4x4 warps) ----------------
// WRITE_MODE 0: hout16 = half(relu(...)*norm_src) ; 1: outf = relu(...) (final fp32)
#define PADK 136
#define A_IMG_BYTES (128 * PADK * 2)
#define GEMM_SMEM (2 * A_IMG_BYTES)

__device__ __forceinline__ void mma_bf16(float& c0, float& c1, float& c2, float& c3,
                                         uint32_t a0, uint32_t a1, uint32_t a2, uint32_t a3,
                                         uint32_t b0, uint32_t b1) {
    asm volatile(
        "mma.sync.aligned.m16n8k16.row.col.f32.bf16.bf16.f32 "
        "{%0,%1,%2,%3}, {%4,%5,%6,%7}, {%8,%9}, {%0,%1,%2,%3};"
        : "+f"(c0), "+f"(c1), "+f"(c2), "+f"(c3)
        : "r"(a0), "r"(a1), "r"(a2), "r"(a3), "r"(b0), "r"(b1));
}

template <int WRITE_MODE>
__global__ __launch_bounds__(512, 2)
void mma_gemm_kernel(__half* __restrict__ hout16, float* __restrict__ outf,
                     const float* __restrict__ bias, const uint2* __restrict__ Bfrag) {
    extern __shared__ char smem[];
    __nv_bfloat16* sAhi = (__nv_bfloat16*)smem;
    __nv_bfloat16* sAlo = (__nv_bfloat16*)(smem + A_IMG_BYTES);

    int tid = threadIdx.x;
    int wid = tid >> 5, lane = tid & 31;
    int warp_m = wid >> 2, warp_n = wid & 3;      // 4x4 warp grid
    int g = lane >> 2, tig = lane & 3;
    int row0 = blockIdx.x * 128;

    // ---- load A tile (coalesced stream from g_agg), bf16 split into smem ----
    #pragma unroll
    for (int it = 0; it < 8; it++) {
        int i = tid + it * 512;
        int r = i >> 5, c4 = i & 31;
        int gr = row0 + r;
        float4 v = make_float4(0.f, 0.f, 0.f, 0.f);
        if (gr < N_NODES)
            v = ((const float4*)(g_agg + (size_t)gr * DIM))[c4];
        __nv_bfloat16 h0, l0, h1, l1, h2, l2, h3, l3;
        bf16_split(v.x, h0, l0); bf16_split(v.y, h1, l1);
        bf16_split(v.z, h2, l2); bf16_split(v.w, h3, l3);
        uint32_t off = (uint32_t)r * PADK + (uint32_t)c4 * 4;
        *(uint2*)(sAhi + off) = make_uint2(pack2(h0, h1), pack2(h2, h3));
        *(uint2*)(sAlo + off) = make_uint2(pack2(l0, l1), pack2(l2, l3));
    }
    __syncthreads();

    // ---- MMA: warp tile 32 rows x 32 cols ----
    float acc[2][4][4];
    #pragma unroll
    for (int mt = 0; mt < 2; mt++)
        #pragma unroll
        for (int nt = 0; nt < 4; nt++)
            #pragma unroll
            for (int q = 0; q < 4; q++) acc[mt][nt][q] = 0.f;

    const int rbase = warp_m * 32;
    #pragma unroll
    for (int ks = 0; ks < 8; ks++) {
        int kc = ks * 16 + 2 * tig;
        uint32_t ahi[2][4], alo[2][4];
        #pragma unroll
        for (int mt = 0; mt < 2; mt++) {
            int rb = rbase + mt * 16 + g;
            const __nv_bfloat16* ph = sAhi + (uint32_t)rb * PADK + kc;
            const __nv_bfloat16* pl = sAlo + (uint32_t)rb * PADK + kc;
            ahi[mt][0] = *(const uint32_t*)(ph);
            ahi[mt][1] = *(const uint32_t*)(ph + 8 * PADK);
            ahi[mt][2] = *(const uint32_t*)(ph + 8);
            ahi[mt][3] = *(const uint32_t*)(ph + 8 * PADK + 8);
            alo[mt][0] = *(const uint32_t*)(pl);
            alo[mt][1] = *(const uint32_t*)(pl + 8 * PADK);
            alo[mt][2] = *(const uint32_t*)(pl + 8);
            alo[mt][3] = *(const uint32_t*)(pl + 8 * PADK + 8);
        }
        uint2 bh[4], bl[4];
        #pragma unroll
        for (int j = 0; j < 4; j++) {
            int ntg = warp_n * 4 + j;
            const uint2* bp = Bfrag + ((size_t)(ks * 16 + ntg) * 2) * 32 + lane;
            bh[j] = __ldg(bp);
            bl[j] = __ldg(bp + 32);
        }
        #pragma unroll
        for (int j = 0; j < 4; j++) {
            #pragma unroll
            for (int mt = 0; mt < 2; mt++) {
                float* c = acc[mt][j];
                mma_bf16(c[0], c[1], c[2], c[3],
                         ahi[mt][0], ahi[mt][1], ahi[mt][2], ahi[mt][3], bh[j].x, bh[j].y);
                mma_bf16(c[0], c[1], c[2], c[3],
                         ahi[mt][0], ahi[mt][1], ahi[mt][2], ahi[mt][3], bl[j].x, bl[j].y);
                mma_bf16(c[0], c[1], c[2], c[3],
                         alo[mt][0], alo[mt][1], alo[mt][2], alo[mt][3], bh[j].x, bh[j].y);
            }
        }
    }

    // ---- epilogue: bias + relu (+ norm_src fold), write fp16 (or final fp32) ----
    #pragma unroll
    for (int mt = 0; mt < 2; mt++) {
        int ra = row0 + rbase + mt * 16 + g;
        int rb = ra + 8;
        bool va = ra < N_NODES, vb = rb < N_NODES;
        float nsa = 1.f, nsb = 1.f;
        if (WRITE_MODE == 0) {
            if (va) nsa = g_norm_src[ra];
            if (vb) nsb = g_norm_src[rb];
        }
        #pragma unroll
        for (int nt = 0; nt < 4; nt++) {
            int col = warp_n * 32 + nt * 8 + 2 * tig;
            float2 b2 = __ldg((const float2*)(bias + col));
            float* c = acc[mt][nt];
            if (WRITE_MODE == 0) {
                if (va) {
                    __half2 o = __floats2half2_rn(fmaxf(c[0] + b2.x, 0.f) * nsa,
                                                  fmaxf(c[1] + b2.y, 0.f) * nsa);
                    *(__half2*)(hout16 + (size_t)ra * DIM + col) = o;
                }
                if (vb) {
                    __half2 o = __floats2half2_rn(fmaxf(c[2] + b2.x, 0.f) * nsb,
                                                  fmaxf(c[3] + b2.y, 0.f) * nsb);
                    *(__half2*)(hout16 + (size_t)rb * DIM + col) = o;
                }
            } else {
                if (va) {
                    float2 o;
                    o.x = fmaxf(c[0] + b2.x, 0.f);
                    o.y = fmaxf(c[1] + b2.y, 0.f);
                    *(float2*)(outf + (size_t)ra * DIM + col) = o;
                }
                if (vb) {
                    float2 o;
                    o.x = fmaxf(c[2] + b2.x, 0.f);
                    o.y = fmaxf(c[3] + b2.y, 0.f);
                    *(float2*)(outf + (size_t)rb * DIM + col) = o;
                }
            }
        }
    }
}

// ---------------- launcher ----------------
extern "C" void kernel_launch(void* const* d_in, const int* in_sizes, int n_in,
                              void* d_out, int out_size) {
    const int*   batch = (const int*)  d_in[0];
    const int*   src   = (const int*)  d_in[1];
    const int*   dst   = (const int*)  d_in[2];
    const float* emb   = (const float*)d_in[3];
    const float* W1    = (const float*)d_in[4];
    const float* b1    = (const float*)d_in[5];
    const float* W2    = (const float*)d_in[6];
    const float* b2    = (const float*)d_in[7];
    const float* W3    = (const float*)d_in[8];
    const float* b3    = (const float*)d_in[9];
    float* out = (float*)d_out;
    (void)in_sizes; (void)n_in; (void)out_size;

    cudaFuncSetAttribute(mma_gemm_kernel<0>, cudaFuncAttributeMaxDynamicSharedMemorySize, GEMM_SMEM);
    cudaFuncSetAttribute(mma_gemm_kernel<1>, cudaFuncAttributeMaxDynamicSharedMemorySize, GEMM_SMEM);

    void* bf_ptr = nullptr;  cudaGetSymbolAddress(&bf_ptr, g_Bfrag);
    void* ha_ptr = nullptr;  cudaGetSymbolAddress(&ha_ptr, g_h16a);
    void* hb_ptr = nullptr;  cudaGetSymbolAddress(&hb_ptr, g_h16b);
    const uint2* Bf = (const uint2*)bf_ptr;
    __half* h16a = (__half*)ha_ptr;
    __half* h16b = (__half*)hb_ptr;
    const size_t BF_LAYER = 8 * 16 * 2 * 32;

    // merged prep: emb16 + deg zero + Bfrag
    init_kernel<<<(VOCAB * DIM / 4 + 255) / 256, 256>>>(emb, W1, W2, W3);
    count_deg_kernel<<<(N_EDGES + 255) / 256, 256>>>(src, dst);
    scan_block_norms_kernel<<<NB, SCAN_BLK>>>();
    scan_tops_kernel<<<1, 128>>>();
    scan_add_kernel<<<NB, SCAN_BLK>>>();
    fill_csr_kernel<<<(N_EDGES + 255) / 256, 256>>>(src, dst);

    const int agg_blocks = (N_NODES * 32 + 255) / 256;
    const int gemm_blocks = (N_NODES + 127) / 128;

    // layer 1: (emb16, batch) -> agg -> h16a
    aggregate_emb_kernel<<<agg_blocks, 256>>>(batch);
    mma_gemm_kernel<0><<<gemm_blocks, 512, GEMM_SMEM>>>(h16a, nullptr, b1, Bf + 0 * BF_LAYER);
    // layer 2: h16a -> agg -> h16b
    aggregate_kernel<<<agg_blocks, 256>>>(h16a);
    mma_gemm_kernel<0><<<gemm_blocks, 512, GEMM_SMEM>>>(h16b, nullptr, b2, Bf + 1 * BF_LAYER);
    // layer 3: h16b -> agg -> out (final fp32)
    aggregate_kernel<<<agg_blocks, 256>>>(h16b);
    mma_gemm_kernel<1><<<gemm_blocks, 512, GEMM_SMEM>>>(nullptr, out, b3, Bf + 2 * BF_LAYER);
}

// round 14
// speedup vs baseline: 1.3215x; 1.0133x over previous
#include <cuda_runtime.h>
#include <cuda_bf16.h>
#include <cuda_fp16.h>
#include <cstdint>

#define N_NODES 50000
#define N_EDGES 800000
#define DIM 128
#define VOCAB 50000
#define SCAN_BLK 512
#define NB ((N_NODES + SCAN_BLK - 1) / SCAN_BLK)   // 98

// ---------------- device scratch (static, allocation-free, zero-initialized) ----
__device__ __half g_h16a[(size_t)N_NODES * DIM];   // feature ping (fp16)
__device__ __half g_h16b[(size_t)N_NODES * DIM];   // feature pong (fp16)
__device__ __half g_emb16[(size_t)VOCAB * DIM];    // fp16 copy of emb table
__device__ float  g_agg[(size_t)N_NODES * DIM];    // normalized aggregate (fp32)
__device__ float  g_norm_src[N_NODES];
__device__ float  g_norm_dst[N_NODES];
__device__ int    g_deg[2 * N_NODES];              // invariant: zero at kernel_launch entry
__device__ int    g_row_ptr[N_NODES + 1];          // CSR by dst
__device__ int    g_cursor[N_NODES];
__device__ int    g_blocksum[NB];
__device__ int    g_csr_src[N_EDGES];
// W fragment images: [layer][kstep(8)][ntile(16)][img(2)][lane(32)] of uint2
__device__ uint2  g_Bfrag[3 * 8 * 16 * 2 * 32];

__device__ __forceinline__ void bf16_split(float v, __nv_bfloat16& hi, __nv_bfloat16& lo) {
    hi = __float2bfloat16_rn(v);
    lo = __float2bfloat16_rn(v - __bfloat162float(hi));
}
__device__ __forceinline__ uint32_t pack2(__nv_bfloat16 a, __nv_bfloat16 b) {
    __nv_bfloat162 p = __halves2bfloat162(a, b);
    return *(uint32_t*)&p;
}

// ---------------- degree count (g_deg zeroed by previous replay's scan) ----------------
__global__ void count_deg_kernel(const int* __restrict__ src, const int* __restrict__ dst) {
    int e = blockIdx.x * blockDim.x + threadIdx.x;
    if (e < N_EDGES) {
        atomicAdd(&g_deg[src[e]], 1);
        atomicAdd(&g_deg[N_NODES + dst[e]], 1);
    }
}

// ---------------- merged init: conv_emb + build_Bfrag ----------------
__global__ void init_kernel(const float* __restrict__ emb,
                            const float* __restrict__ W1, const float* __restrict__ W2,
                            const float* __restrict__ W3) {
    int i = blockIdx.x * blockDim.x + threadIdx.x;

    // job 1: emb -> fp16 copy (4 elems/thread)
    if (i < VOCAB * DIM / 4) {
        float4 v = __ldg((const float4*)emb + i);
        __half2 a = __floats2half2_rn(v.x, v.y);
        __half2 b = __floats2half2_rn(v.z, v.w);
        ((uint2*)g_emb16)[i] = make_uint2(*(uint32_t*)&a, *(uint32_t*)&b);
    }
    // job 2: B fragment images for mma.m16n8k16 .col B
    if (i < 3 * 8 * 16 * 32) {
        int layer = i >> 12;
        int rem = i & 4095;
        int ks = rem >> 9;
        int nt = (rem >> 5) & 15;
        int lane = rem & 31;
        int g = lane >> 2, tig = lane & 3;
        const float* W = (layer == 0) ? W1 : (layer == 1) ? W2 : W3;
        int n = nt * 8 + g;
        int k0 = ks * 16 + 2 * tig;
        float w00 = W[(k0 + 0) * DIM + n];
        float w01 = W[(k0 + 1) * DIM + n];
        float w10 = W[(k0 + 8) * DIM + n];
        float w11 = W[(k0 + 9) * DIM + n];
        __nv_bfloat16 h00, l00, h01, l01, h10, l10, h11, l11;
        bf16_split(w00, h00, l00); bf16_split(w01, h01, l01);
        bf16_split(w10, h10, l10); bf16_split(w11, h11, l11);
        int idx = (layer * 8 + ks) * 16 + nt;
        g_Bfrag[(idx * 2 + 0) * 32 + lane] = make_uint2(pack2(h00, h01), pack2(h10, h11));
        g_Bfrag[(idx * 2 + 1) * 32 + lane] = make_uint2(pack2(l00, l01), pack2(l10, l11));
    }
}

// ---- scan_block + norms + deg re-zero (maintains zero-at-entry invariant) ----
__global__ void scan_block_norms_kernel() {
    __shared__ int sdata[SCAN_BLK];
    int i = blockIdx.x * SCAN_BLK + threadIdx.x;
    int v = 0;
    if (i < N_NODES) {
        int din = g_deg[N_NODES + i];
        int dout = g_deg[i];
        v = din;
        g_norm_src[i] = rsqrtf((float)max(dout, 1));
        g_norm_dst[i] = rsqrtf((float)max(din, 1));
        g_deg[i] = 0;
        g_deg[N_NODES + i] = 0;
    }
    sdata[threadIdx.x] = v;
    __syncthreads();
    for (int off = 1; off < SCAN_BLK; off <<= 1) {
        int t = (threadIdx.x >= off) ? sdata[threadIdx.x - off] : 0;
        __syncthreads();
        sdata[threadIdx.x] += t;
        __syncthreads();
    }
    if (i < N_NODES) g_row_ptr[i + 1] = sdata[threadIdx.x];
    if (threadIdx.x == SCAN_BLK - 1) g_blocksum[blockIdx.x] = sdata[SCAN_BLK - 1];
}

// finalizes row_ptr (inline prefix of blocksums) AND seeds cursor
__global__ void scan_add_kernel() {
    __shared__ int sdata[SCAN_BLK];
    int tid = threadIdx.x;
    int v = (tid < NB && tid < blockIdx.x) ? g_blocksum[tid] : 0;
    sdata[tid] = v;
    __syncthreads();
    #pragma unroll
    for (int off = 256; off > 0; off >>= 1) {
        if (tid < off) sdata[tid] += sdata[tid + off];
        __syncthreads();
    }
    int base = sdata[0];   // sum of blocksums before this block
    int i = blockIdx.x * SCAN_BLK + tid;
    if (i < N_NODES) {
        int rv = g_row_ptr[i + 1] + base;
        g_row_ptr[i + 1] = rv;
        if (i + 1 < N_NODES) g_cursor[i + 1] = rv;
    }
    if (i == 0) { g_row_ptr[0] = 0; g_cursor[0] = 0; }
}

__global__ void fill_csr_kernel(const int* __restrict__ src, const int* __restrict__ dst) {
    int e = blockIdx.x * blockDim.x + threadIdx.x;
    if (e < N_EDGES) {
        int pos = atomicAdd(&g_cursor[dst[e]], 1);
        g_csr_src[pos] = src[e];
    }
}

// ---------------- aggregation kernels (fp16 features, fp32 accumulation) ----------------
__device__ __forceinline__ void acc_h4(float& ax, float& ay, float& az, float& aw,
                                       uint2 u, float s) {
    __half2 p0 = *(__half2*)&u.x;
    __half2 p1 = *(__half2*)&u.y;
    float2 f0 = __half22float2(p0);
    float2 f1 = __half22float2(p1);
    ax += f0.x * s; ay += f0.y * s; az += f1.x * s; aw += f1.y * s;
}

// Layer 1: g_agg[r] = norm_dst[r] * sum_e emb16[batch[src_e]] * norm_src[src_e]
__global__ __launch_bounds__(256)
void aggregate_emb_kernel(const int* __restrict__ batch) {
    int t = blockIdx.x * blockDim.x + threadIdx.x;
    int gr = t >> 5;
    int lane = t & 31;
    if (gr >= N_NODES) return;

    int beg = __ldg(g_row_ptr + gr);
    int end = __ldg(g_row_ptr + gr + 1);
    float ax = 0.f, ay = 0.f, az = 0.f, aw = 0.f;
    int j = beg;
    for (; j + 3 < end; j += 4) {
        int s0 = __ldg(g_csr_src + j);
        int s1 = __ldg(g_csr_src + j + 1);
        int s2 = __ldg(g_csr_src + j + 2);
        int s3 = __ldg(g_csr_src + j + 3);
        int b0 = __ldg(batch + s0), b1 = __ldg(batch + s1);
        int b2 = __ldg(batch + s2), b3 = __ldg(batch + s3);
        float n0 = __ldg(g_norm_src + s0), n1 = __ldg(g_norm_src + s1);
        float n2 = __ldg(g_norm_src + s2), n3 = __ldg(g_norm_src + s3);
        uint2 u0 = __ldg((const uint2*)(g_emb16 + (size_t)b0 * DIM) + lane);
        uint2 u1 = __ldg((const uint2*)(g_emb16 + (size_t)b1 * DIM) + lane);
        uint2 u2 = __ldg((const uint2*)(g_emb16 + (size_t)b2 * DIM) + lane);
        uint2 u3 = __ldg((const uint2*)(g_emb16 + (size_t)b3 * DIM) + lane);
        acc_h4(ax, ay, az, aw, u0, n0);
        acc_h4(ax, ay, az, aw, u1, n1);
        acc_h4(ax, ay, az, aw, u2, n2);
        acc_h4(ax, ay, az, aw, u3, n3);
    }
    for (; j < end; j++) {
        int s0 = __ldg(g_csr_src + j);
        int b0 = __ldg(batch + s0);
        float n0 = __ldg(g_norm_src + s0);
        uint2 u0 = __ldg((const uint2*)(g_emb16 + (size_t)b0 * DIM) + lane);
        acc_h4(ax, ay, az, aw, u0, n0);
    }
    float nd = __ldg(g_norm_dst + gr);
    ((float4*)(g_agg + (size_t)gr * DIM))[lane] = make_float4(ax * nd, ay * nd, az * nd, aw * nd);
}

// Layers 2-3: g_agg[r] = norm_dst[r] * sum_e hin16[src_e]
__global__ __launch_bounds__(256)
void aggregate_kernel(const __half* __restrict__ hin) {
    int t = blockIdx.x * blockDim.x + threadIdx.x;
    int gr = t >> 5;
    int lane = t & 31;
    if (gr >= N_NODES) return;

    int beg = __ldg(g_row_ptr + gr);
    int end = __ldg(g_row_ptr + gr + 1);
    float ax = 0.f, ay = 0.f, az = 0.f, aw = 0.f;
    int j = beg;
    for (; j + 3 < end; j += 4) {
        int s0 = __ldg(g_csr_src + j);
        int s1 = __ldg(g_csr_src + j + 1);
        int s2 = __ldg(g_csr_src + j + 2);
        int s3 = __ldg(g_csr_src + j + 3);
        uint2 u0 = __ldg((const uint2*)(hin + (size_t)s0 * DIM) + lane);
        uint2 u1 = __ldg((const uint2*)(hin + (size_t)s1 * DIM) + lane);
        uint2 u2 = __ldg((const uint2*)(hin + (size_t)s2 * DIM) + lane);
        uint2 u3 = __ldg((const uint2*)(hin + (size_t)s3 * DIM) + lane);
        acc_h4(ax, ay, az, aw, u0, 1.f);
        acc_h4(ax, ay, az, aw, u1, 1.f);
        acc_h4(ax, ay, az, aw, u2, 1.f);
        acc_h4(ax, ay, az, aw, u3, 1.f);
    }
    for (; j < end; j++) {
        int s0 = __ldg(g_csr_src + j);
        uint2 u0 = __ldg((const uint2*)(hin + (size_t)s0 * DIM) + lane);
        acc_h4(ax, ay, az, aw, u0, 1.f);
    }
    float nd = __ldg(g_norm_dst + gr);
    ((float4*)(g_agg + (size_t)gr * DIM))[lane] = make_float4(ax * nd, ay * nd, az * nd, aw * nd);
}

// ---------------- bf16-split mma GEMM: 64-row CTA tile, 256 thr, 2x4 warps ----------------
// WRITE_MODE 0: hout16 = half(relu(...)*norm_src) ; 1: outf = relu(...) (final fp32)
#define TILE_M 64
#define PADK 136
#define A_IMG_BYTES (TILE_M * PADK * 2)
#define GEMM_SMEM (2 * A_IMG_BYTES)

__device__ __forceinline__ void mma_bf16(float& c0, float& c1, float& c2, float& c3,
                                         uint32_t a0, uint32_t a1, uint32_t a2, uint32_t a3,
                                         uint32_t b0, uint32_t b1) {
    asm volatile(
        "mma.sync.aligned.m16n8k16.row.col.f32.bf16.bf16.f32 "
        "{%0,%1,%2,%3}, {%4,%5,%6,%7}, {%8,%9}, {%0,%1,%2,%3};"
        : "+f"(c0), "+f"(c1), "+f"(c2), "+f"(c3)
        : "r"(a0), "r"(a1), "r"(a2), "r"(a3), "r"(b0), "r"(b1));
}

template <int WRITE_MODE>
__global__ __launch_bounds__(256, 4)
void mma_gemm_kernel(__half* __restrict__ hout16, float* __restrict__ outf,
                     const float* __restrict__ bias, const uint2* __restrict__ Bfrag) {
    extern __shared__ char smem[];
    __nv_bfloat16* sAhi = (__nv_bfloat16*)smem;
    __nv_bfloat16* sAlo = (__nv_bfloat16*)(smem + A_IMG_BYTES);

    int tid = threadIdx.x;
    int wid = tid >> 5, lane = tid & 31;
    int warp_m = wid >> 2, warp_n = wid & 3;      // 2x4 warp grid
    int g = lane >> 2, tig = lane & 3;
    int row0 = blockIdx.x * TILE_M;

    // ---- load A tile (coalesced stream from g_agg), bf16 split into smem ----
    #pragma unroll
    for (int it = 0; it < 8; it++) {
        int i = tid + it * 256;           // 0..2047 float4 chunks (64 rows x 32)
        int r = i >> 5, c4 = i & 31;
        int gr = row0 + r;
        float4 v = make_float4(0.f, 0.f, 0.f, 0.f);
        if (gr < N_NODES)
            v = ((const float4*)(g_agg + (size_t)gr * DIM))[c4];
        __nv_bfloat16 h0, l0, h1, l1, h2, l2, h3, l3;
        bf16_split(v.x, h0, l0); bf16_split(v.y, h1, l1);
        bf16_split(v.z, h2, l2); bf16_split(v.w, h3, l3);
        uint32_t off = (uint32_t)r * PADK + (uint32_t)c4 * 4;
        *(uint2*)(sAhi + off) = make_uint2(pack2(h0, h1), pack2(h2, h3));
        *(uint2*)(sAlo + off) = make_uint2(pack2(l0, l1), pack2(l2, l3));
    }
    __syncthreads();

    // ---- MMA: warp tile 32 rows x 32 cols ----
    float acc[2][4][4];
    #pragma unroll
    for (int mt = 0; mt < 2; mt++)
        #pragma unroll
        for (int nt = 0; nt < 4; nt++)
            #pragma unroll
            for (int q = 0; q < 4; q++) acc[mt][nt][q] = 0.f;

    const int rbase = warp_m * 32;
    #pragma unroll
    for (int ks = 0; ks < 8; ks++) {
        int kc = ks * 16 + 2 * tig;
        uint32_t ahi[2][4], alo[2][4];
        #pragma unroll
        for (int mt = 0; mt < 2; mt++) {
            int rb = rbase + mt * 16 + g;
            const __nv_bfloat16* ph = sAhi + (uint32_t)rb * PADK + kc;
            const __nv_bfloat16* pl = sAlo + (uint32_t)rb * PADK + kc;
            ahi[mt][0] = *(const uint32_t*)(ph);
            ahi[mt][1] = *(const uint32_t*)(ph + 8 * PADK);
            ahi[mt][2] = *(const uint32_t*)(ph + 8);
            ahi[mt][3] = *(const uint32_t*)(ph + 8 * PADK + 8);
            alo[mt][0] = *(const uint32_t*)(pl);
            alo[mt][1] = *(const uint32_t*)(pl + 8 * PADK);
            alo[mt][2] = *(const uint32_t*)(pl + 8);
            alo[mt][3] = *(const uint32_t*)(pl + 8 * PADK + 8);
        }
        uint2 bh[4], bl[4];
        #pragma unroll
        for (int j = 0; j < 4; j++) {
            int ntg = warp_n * 4 + j;
            const uint2* bp = Bfrag + ((size_t)(ks * 16 + ntg) * 2) * 32 + lane;
            bh[j] = __ldg(bp);
            bl[j] = __ldg(bp + 32);
        }
        #pragma unroll
        for (int j = 0; j < 4; j++) {
            #pragma unroll
            for (int mt = 0; mt < 2; mt++) {
                float* c = acc[mt][j];
                mma_bf16(c[0], c[1], c[2], c[3],
                         ahi[mt][0], ahi[mt][1], ahi[mt][2], ahi[mt][3], bh[j].x, bh[j].y);
                mma_bf16(c[0], c[1], c[2], c[3],
                         ahi[mt][0], ahi[mt][1], ahi[mt][2], ahi[mt][3], bl[j].x, bl[j].y);
                mma_bf16(c[0], c[1], c[2], c[3],
                         alo[mt][0], alo[mt][1], alo[mt][2], alo[mt][3], bh[j].x, bh[j].y);
            }
        }
    }

    // ---- epilogue: bias + relu (+ norm_src fold), write fp16 (or final fp32) ----
    #pragma unroll
    for (int mt = 0; mt < 2; mt++) {
        int ra = row0 + rbase + mt * 16 + g;
        int rb = ra + 8;
        bool va = ra < N_NODES, vb = rb < N_NODES;
        float nsa = 1.f, nsb = 1.f;
        if (WRITE_MODE == 0) {
            if (va) nsa = g_norm_src[ra];
            if (vb) nsb = g_norm_src[rb];
        }
        #pragma unroll
        for (int nt = 0; nt < 4; nt++) {
            int col = warp_n * 32 + nt * 8 + 2 * tig;
            float2 b2 = __ldg((const float2*)(bias + col));
            float* c = acc[mt][nt];
            if (WRITE_MODE == 0) {
                if (va) {
                    __half2 o = __floats2half2_rn(fmaxf(c[0] + b2.x, 0.f) * nsa,
                                                  fmaxf(c[1] + b2.y, 0.f) * nsa);
                    *(__half2*)(hout16 + (size_t)ra * DIM + col) = o;
                }
                if (vb) {
                    __half2 o = __floats2half2_rn(fmaxf(c[2] + b2.x, 0.f) * nsb,
                                                  fmaxf(c[3] + b2.y, 0.f) * nsb);
                    *(__half2*)(hout16 + (size_t)rb * DIM + col) = o;
                }
            } else {
                if (va) {
                    float2 o;
                    o.x = fmaxf(c[0] + b2.x, 0.f);
                    o.y = fmaxf(c[1] + b2.y, 0.f);
                    *(float2*)(outf + (size_t)ra * DIM + col) = o;
                }
                if (vb) {
                    float2 o;
                    o.x = fmaxf(c[2] + b2.x, 0.f);
                    o.y = fmaxf(c[3] + b2.y, 0.f);
                    *(float2*)(outf + (size_t)rb * DIM + col) = o;
                }
            }
        }
    }
}

// ---------------- launcher ----------------
extern "C" void kernel_launch(void* const* d_in, const int* in_sizes, int n_in,
                              void* d_out, int out_size) {
    const int*   batch = (const int*)  d_in[0];
    const int*   src   = (const int*)  d_in[1];
    const int*   dst   = (const int*)  d_in[2];
    const float* emb   = (const float*)d_in[3];
    const float* W1    = (const float*)d_in[4];
    const float* b1    = (const float*)d_in[5];
    const float* W2    = (const float*)d_in[6];
    const float* b2    = (const float*)d_in[7];
    const float* W3    = (const float*)d_in[8];
    const float* b3    = (const float*)d_in[9];
    float* out = (float*)d_out;
    (void)in_sizes; (void)n_in; (void)out_size;

    cudaFuncSetAttribute(mma_gemm_kernel<0>, cudaFuncAttributeMaxDynamicSharedMemorySize, GEMM_SMEM);
    cudaFuncSetAttribute(mma_gemm_kernel<1>, cudaFuncAttributeMaxDynamicSharedMemorySize, GEMM_SMEM);

    void* bf_ptr = nullptr;  cudaGetSymbolAddress(&bf_ptr, g_Bfrag);
    void* ha_ptr = nullptr;  cudaGetSymbolAddress(&ha_ptr, g_h16a);
    void* hb_ptr = nullptr;  cudaGetSymbolAddress(&hb_ptr, g_h16b);
    const uint2* Bf = (const uint2*)bf_ptr;
    __half* h16a = (__half*)ha_ptr;
    __half* h16b = (__half*)hb_ptr;
    const size_t BF_LAYER = 8 * 16 * 2 * 32;

    // prep: count (deg zero-at-entry invariant), init, scan(+norms+rezero), add(+tops), fill
    count_deg_kernel<<<(N_EDGES + 255) / 256, 256>>>(src, dst);
    init_kernel<<<(VOCAB * DIM / 4 + 255) / 256, 256>>>(emb, W1, W2, W3);
    scan_block_norms_kernel<<<NB, SCAN_BLK>>>();
    scan_add_kernel<<<NB, SCAN_BLK>>>();
    fill_csr_kernel<<<(N_EDGES + 255) / 256, 256>>>(src, dst);

    const int agg_blocks = (N_NODES * 32 + 255) / 256;
    const int gemm_blocks = (N_NODES + TILE_M - 1) / TILE_M;

    // layer 1: (emb16, batch) -> agg -> h16a
    aggregate_emb_kernel<<<agg_blocks, 256>>>(batch);
    mma_gemm_kernel<0><<<gemm_blocks, 256, GEMM_SMEM>>>(h16a, nullptr, b1, Bf + 0 * BF_LAYER);
    // layer 2: h16a -> agg -> h16b
    aggregate_kernel<<<agg_blocks, 256>>>(h16a);
    mma_gemm_kernel<0><<<gemm_blocks, 256, GEMM_SMEM>>>(h16b, nullptr, b2, Bf + 1 * BF_LAYER);
    // layer 3: h16b -> agg -> out (final fp32)
    aggregate_kernel<<<agg_blocks, 256>>>(h16b);
    mma_gemm_kernel<1><<<gemm_blocks, 256, GEMM_SMEM>>>(nullptr, out, b3, Bf + 2 * BF_LAYER);
}